// round 12
// baseline (speedup 1.0000x reference)
#include <cuda_runtime.h>
#include <cuda_bf16.h>
#include <cstdint>

#define NN 100000
#define ROWSP 100096           // NN padded to multiple of 128
#define NE 3200000
#define IND 512
#define HID 256
#define NC  64

// ---------------- scratch (static device globals; no runtime allocation) ----
__device__ float g_tb[3][(size_t)NN * NC];                     // rotating T_k buffers
__device__ int   g_rp[NN + 1];                                 // CSR row_ptr
__device__ __align__(128) __nv_bfloat16 g_ahi[(size_t)8 * ROWSP * 64];
__device__ __align__(128) __nv_bfloat16 g_alo[(size_t)8 * ROWSP * 64];
__device__ __align__(128) __nv_bfloat16 g_hhi[(size_t)4 * ROWSP * 64];
__device__ __align__(128) __nv_bfloat16 g_hlo[(size_t)4 * ROWSP * 64];
__device__ __align__(128) __nv_bfloat16 g_w1hi[8 * 256 * 64], g_w1lo[8 * 256 * 64];
__device__ __align__(128) __nv_bfloat16 g_w2hi[4 * 64 * 64],  g_w2lo[4 * 64 * 64];

// ---------------- inline PTX helpers (base ISA only) ------------------------
__device__ __forceinline__ uint32_t smem_u32(const void* p) {
    uint32_t a;
    asm("{ .reg .u64 t; cvta.to.shared.u64 t, %1; cvt.u32.u64 %0, t; }" : "=r"(a) : "l"(p));
    return a;
}
#define MBARRIER_INIT(addr, cnt) \
    asm volatile("mbarrier.init.shared.b64 [%0], %1;" :: "r"(addr), "r"((uint32_t)(cnt)) : "memory")
#define MBARRIER_INVAL(addr) \
    asm volatile("mbarrier.inval.shared.b64 [%0];" :: "r"(addr) : "memory")
#define MBARRIER_EXPECT_TX(addr, bytes) \
    asm volatile("mbarrier.arrive.expect_tx.shared.b64 _, [%0], %1;" :: "r"(addr), "r"((uint32_t)(bytes)) : "memory")
__device__ __forceinline__ void mbar_wait(uint32_t mbar, uint32_t parity) {
    asm volatile(
        "{\n\t.reg .pred P1;\n\t"
        "WAIT_LOOP_%=:\n\t"
        "mbarrier.try_wait.parity.acquire.cta.shared::cta.b64 P1, [%0], %1, 0x989680;\n\t"
        "@P1 bra.uni WAIT_DONE_%=;\n\t"
        "bra.uni WAIT_LOOP_%=;\n\t"
        "WAIT_DONE_%=:\n\t}"
        :: "r"(mbar), "r"(parity) : "memory");
}
#define BULK_G2S(dst, src, bytes, mbar) \
    asm volatile("cp.async.bulk.shared::cta.global.mbarrier::complete_tx::bytes [%0], [%1], %2, [%3];" \
        :: "r"((uint32_t)(dst)), "l"(src), "r"((uint32_t)(bytes)), "r"((uint32_t)(mbar)) : "memory")

__device__ __forceinline__ void ldsm4(uint32_t* r, uint32_t addr) {
    asm volatile("ldmatrix.sync.aligned.m8n8.x4.shared.b16 {%0,%1,%2,%3}, [%4];"
        : "=r"(r[0]), "=r"(r[1]), "=r"(r[2]), "=r"(r[3]) : "r"(addr));
}
__device__ __forceinline__ void mma_bf16(float* d, const uint32_t* a, const uint32_t* b) {
    asm volatile("mma.sync.aligned.m16n8k16.row.col.f32.bf16.bf16.f32 "
        "{%0,%1,%2,%3}, {%4,%5,%6,%7}, {%8,%9}, {%0,%1,%2,%3};"
        : "+f"(d[0]), "+f"(d[1]), "+f"(d[2]), "+f"(d[3])
        : "r"(a[0]), "r"(a[1]), "r"(a[2]), "r"(a[3]), "r"(b[0]), "r"(b[1]));
}

// ---------------- prep kernels ----------------------------------------------
template <int KSHIFT>
__global__ void prep_a(const float* __restrict__ src,
                       __nv_bfloat16* __restrict__ dhi, __nv_bfloat16* __restrict__ dlo) {
    constexpr int K = 1 << KSHIFT;
    constexpr int G = K / 8;
    long long idx = (long long)blockIdx.x * blockDim.x + threadIdx.x;
    if (idx >= (long long)NN * G) return;
    int r = (int)(idx / G);
    int g = (int)(idx % G);
    int k = g * 8;
    int c = k >> 6, kk = k & 63;

    const float4* s4 = (const float4*)(src + (size_t)r * K + k);
    float4 v0 = s4[0], v1 = s4[1];
    float f[8] = {v0.x, v0.y, v0.z, v0.w, v1.x, v1.y, v1.z, v1.w};
    __nv_bfloat162 hi[4], lo[4];
#pragma unroll
    for (int i = 0; i < 4; ++i) {
        __nv_bfloat16 h0 = __float2bfloat16(f[2 * i]);
        __nv_bfloat16 h1 = __float2bfloat16(f[2 * i + 1]);
        hi[i] = __nv_bfloat162(h0, h1);
        lo[i] = __nv_bfloat162(__float2bfloat16(f[2 * i] - __bfloat162float(h0)),
                               __float2bfloat16(f[2 * i + 1] - __bfloat162float(h1)));
    }
    uint32_t off = (uint32_t)r * 128 + (((uint32_t)kk * 2) ^ (((uint32_t)r & 7) << 4));
    size_t pbase = (size_t)c * ROWSP * 128;
    *(uint4*)((char*)dhi + pbase + off) = *(uint4*)hi;
    *(uint4*)((char*)dlo + pbase + off) = *(uint4*)lo;
}

template <int NSHIFT>
__global__ void prep_w(const float* __restrict__ src, int K,
                       __nv_bfloat16* __restrict__ dhi, __nv_bfloat16* __restrict__ dlo) {
    constexpr int N = 1 << NSHIFT;
    int idx = blockIdx.x * blockDim.x + threadIdx.x;
    if (idx >= K * N) return;
    int k = idx >> NSHIFT;
    int n = idx & (N - 1);
    int c = k >> 6, kk = k & 63;
    float v = src[idx];
    __nv_bfloat16 hi = __float2bfloat16(v);
    __nv_bfloat16 lo = __float2bfloat16(v - __bfloat162float(hi));
    int poff = (kk << 1) ^ ((n & 7) << 4);
    size_t dst = ((size_t)c * N + n) * 64 + (poff >> 1);
    dhi[dst] = hi;
    dlo[dst] = lo;
}

// ---------------- split-bf16 mma.sync GEMM ----------------------------------
// D[128, BN] = A[128, K] @ B[BN, K]^T; 3 split products per 64-chunk.
// BN=64, 2-stage, 99328 B smem -> 2 CTAs/SM so sync bubbles overlap.
template <int BN, int NCHUNK, int WM, int WN, bool SPLIT_OUT>
__global__ void __launch_bounds__(256, 2)
tc_gemm(const __nv_bfloat16* __restrict__ Ahi, const __nv_bfloat16* __restrict__ Alo,
        const __nv_bfloat16* __restrict__ Bhi, const __nv_bfloat16* __restrict__ Blo,
        const float* __restrict__ bias, float* __restrict__ C,
        __nv_bfloat16* __restrict__ Ohi, __nv_bfloat16* __restrict__ Olo, int NB) {
    constexpr int WR = 128 / WM;
    constexpr int WC = BN / WN;
    constexpr int MT = WR / 16;
    constexpr int NT = WC / 8;
    constexpr uint32_t BNB = BN * 128;
    constexpr uint32_t BUFB = 32768 + 2 * BNB;

    extern __shared__ char smem[];
    const uint32_t sb = smem_u32(smem);
    const int tid = threadIdx.x;
    const int lane = tid & 31;
    const int wid = tid >> 5;
    const int wm = wid / WN, wn = wid % WN;
    const int bm = blockIdx.y * 128;
    const int n0 = blockIdx.x * BN;            // n fast: 4 CTAs share A tile in L2

    const uint32_t mb0 = sb + 8, mb1 = sb + 24;
    if (tid == 0) { MBARRIER_INIT(mb0, 1); MBARRIER_INIT(mb1, 1); }
    __syncthreads();

    auto issue = [&](int c) {
        int buf = c & 1;
        uint32_t mb = buf ? mb1 : mb0;
        uint32_t base = sb + 1024 + (uint32_t)buf * BUFB;
        MBARRIER_EXPECT_TX(mb, BUFB);
        const char* ah = (const char*)Ahi + ((size_t)c * ROWSP + bm) * 128;
        const char* al = (const char*)Alo + ((size_t)c * ROWSP + bm) * 128;
        const char* bh = (const char*)Bhi + ((size_t)c * NB + n0) * 128;
        const char* bl = (const char*)Blo + ((size_t)c * NB + n0) * 128;
        BULK_G2S(base,               ah, 16384, mb);
        BULK_G2S(base + 16384,       al, 16384, mb);
        BULK_G2S(base + 32768,       bh, BNB,   mb);
        BULK_G2S(base + 32768 + BNB, bl, BNB,   mb);
    };
    if (tid == 0) {
#pragma unroll
        for (int c = 0; c < 2 && c < NCHUNK; ++c) issue(c);
    }

    const int arow = lane & 15;
    const int akb = (lane >> 4) << 3;
    const uint32_t aRowOff = (uint32_t)(wm * WR + arow) * 128;
    const uint32_t aSw = (uint32_t)(arow & 7) << 4;
    const int brow = (lane & 7) + ((lane >> 4) << 3);
    const int bkb = ((lane >> 3) & 1) << 3;
    const uint32_t bRowOff = (uint32_t)(wn * WC + brow) * 128;
    const uint32_t bSw = (uint32_t)(brow & 7) << 4;

    float acc[MT][NT][4];
#pragma unroll
    for (int i = 0; i < MT; ++i)
#pragma unroll
        for (int j = 0; j < NT; ++j)
#pragma unroll
            for (int q = 0; q < 4; ++q) acc[i][j][q] = 0.f;

    for (int c = 0; c < NCHUNK; ++c) {
        const int buf = c & 1;
        mbar_wait(buf ? mb1 : mb0, (uint32_t)(c >> 1) & 1);

        const uint32_t base = sb + 1024 + (uint32_t)buf * BUFB;
        const uint32_t aHiS = base, aLoS = base + 16384;
        const uint32_t bHiS = base + 32768, bLoS = base + 32768 + BNB;

#pragma unroll
        for (int ks = 0; ks < 4; ++ks) {
            uint32_t ah[MT][4], al[MT][4], bh[NT][2], bl[NT][2];
            const uint32_t akByte = ((uint32_t)((ks * 16 + akb) * 2)) ^ aSw;
#pragma unroll
            for (int mt = 0; mt < MT; ++mt) {
                uint32_t o = aRowOff + (uint32_t)mt * 2048 + akByte;
                ldsm4(ah[mt], aHiS + o);
                ldsm4(al[mt], aLoS + o);
            }
            const uint32_t bkByte = ((uint32_t)((ks * 16 + bkb) * 2)) ^ bSw;
#pragma unroll
            for (int p = 0; p < NT / 2; ++p) {
                uint32_t o = bRowOff + (uint32_t)p * 2048 + bkByte;
                uint32_t t[4];
                ldsm4(t, bHiS + o);
                bh[2 * p][0] = t[0]; bh[2 * p][1] = t[1];
                bh[2 * p + 1][0] = t[2]; bh[2 * p + 1][1] = t[3];
                ldsm4(t, bLoS + o);
                bl[2 * p][0] = t[0]; bl[2 * p][1] = t[1];
                bl[2 * p + 1][0] = t[2]; bl[2 * p + 1][1] = t[3];
            }
#pragma unroll
            for (int mt = 0; mt < MT; ++mt)
#pragma unroll
                for (int nt = 0; nt < NT; ++nt)
                    mma_bf16(acc[mt][nt], ah[mt], bh[nt]);
#pragma unroll
            for (int mt = 0; mt < MT; ++mt)
#pragma unroll
                for (int nt = 0; nt < NT; ++nt)
                    mma_bf16(acc[mt][nt], ah[mt], bl[nt]);
#pragma unroll
            for (int mt = 0; mt < MT; ++mt)
#pragma unroll
                for (int nt = 0; nt < NT; ++nt)
                    mma_bf16(acc[mt][nt], al[mt], bh[nt]);
        }
        __syncthreads();
        if (tid == 0 && c + 2 < NCHUNK) issue(c + 2);
    }

    // epilogue
    const int r0 = bm + wm * WR + (lane >> 2);
#pragma unroll
    for (int mt = 0; mt < MT; ++mt) {
#pragma unroll
        for (int nt = 0; nt < NT; ++nt) {
            int row = r0 + mt * 16;
            int col = n0 + wn * WC + nt * 8 + (lane & 3) * 2;
            float bv0 = __ldg(bias + col), bv1 = __ldg(bias + col + 1);
            if (SPLIT_OUT) {
                int pl = col >> 6, kk = col & 63;
                size_t pbase = (size_t)pl * ROWSP * 128;
                uint32_t xoff = ((uint32_t)kk * 2);
#pragma unroll
                for (int half = 0; half < 2; ++half) {
                    int r = row + half * 8;
                    if (r >= NN) continue;
                    float v0 = fmaxf(acc[mt][nt][2 * half + 0] + bv0, 0.f);
                    float v1 = fmaxf(acc[mt][nt][2 * half + 1] + bv1, 0.f);
                    __nv_bfloat16 h0 = __float2bfloat16(v0);
                    __nv_bfloat16 h1 = __float2bfloat16(v1);
                    __nv_bfloat162 hv(h0, h1);
                    __nv_bfloat162 lv(__float2bfloat16(v0 - __bfloat162float(h0)),
                                      __float2bfloat16(v1 - __bfloat162float(h1)));
                    uint32_t off = (uint32_t)r * 128 + (xoff ^ (((uint32_t)r & 7) << 4));
                    *(__nv_bfloat162*)((char*)Ohi + pbase + off) = hv;
                    *(__nv_bfloat162*)((char*)Olo + pbase + off) = lv;
                }
            } else {
#pragma unroll
                for (int half = 0; half < 2; ++half) {
                    int r = row + half * 8;
                    if (r >= NN) continue;
                    float2 v;
                    v.x = acc[mt][nt][2 * half + 0] + bv0;
                    v.y = acc[mt][nt][2 * half + 1] + bv1;
                    *(float2*)&C[(size_t)r * NB + col] = v;
                }
            }
        }
    }
    __syncthreads();
    if (tid == 0) { MBARRIER_INVAL(mb0); MBARRIER_INVAL(mb1); }
}

// ---------------- row_ptr build ---------------------------------------------
__global__ void build_row_ptr(const int* __restrict__ erow) {
    int r = blockIdx.x * blockDim.x + threadIdx.x;
    if (r > NN) return;
    int lo = 0, hi = NE;
    while (lo < hi) {
        int mid = (lo + hi) >> 1;
        if (erow[mid] < r) lo = mid + 1; else hi = mid;
    }
    g_rp[r] = lo;
}

// ---------------- fused CSR SpMM + Chebyshev recurrence ---------------------
// Exact R6-measured version: 16 thr/row, unroll-4, single acc (at L2 roofline).
__global__ void spmm_cheb(const int* __restrict__ ecol, const float* __restrict__ evals,
                          const float* __restrict__ gamma, float* __restrict__ z,
                          int cur, int prev, int nxt, int k, int first, int last) {
    int t = blockIdx.x * blockDim.x + threadIdx.x;
    int row = t >> 4;
    int ch = t & 15;
    if (row >= NN) return;

    const float4* vcur = (const float4*)g_tb[cur];
    int s = g_rp[row];
    int e = g_rp[row + 1];

    float4 acc = make_float4(0.f, 0.f, 0.f, 0.f);
    int i = s;
    int nb = (e - s) >> 2;
    for (int b = 0; b < nb; ++b, i += 4) {
        int c0 = __ldg(ecol + i + 0), c1 = __ldg(ecol + i + 1);
        int c2 = __ldg(ecol + i + 2), c3 = __ldg(ecol + i + 3);
        float w0 = __ldg(evals + i + 0), w1 = __ldg(evals + i + 1);
        float w2 = __ldg(evals + i + 2), w3 = __ldg(evals + i + 3);
        float4 v0 = __ldg(vcur + (size_t)c0 * 16 + ch);
        float4 v1 = __ldg(vcur + (size_t)c1 * 16 + ch);
        float4 v2 = __ldg(vcur + (size_t)c2 * 16 + ch);
        float4 v3 = __ldg(vcur + (size_t)c3 * 16 + ch);
        acc.x = fmaf(w0, v0.x, acc.x); acc.y = fmaf(w0, v0.y, acc.y);
        acc.z = fmaf(w0, v0.z, acc.z); acc.w = fmaf(w0, v0.w, acc.w);
        acc.x = fmaf(w1, v1.x, acc.x); acc.y = fmaf(w1, v1.y, acc.y);
        acc.z = fmaf(w1, v1.z, acc.z); acc.w = fmaf(w1, v1.w, acc.w);
        acc.x = fmaf(w2, v2.x, acc.x); acc.y = fmaf(w2, v2.y, acc.y);
        acc.z = fmaf(w2, v2.z, acc.z); acc.w = fmaf(w2, v2.w, acc.w);
        acc.x = fmaf(w3, v3.x, acc.x); acc.y = fmaf(w3, v3.y, acc.y);
        acc.z = fmaf(w3, v3.z, acc.z); acc.w = fmaf(w3, v3.w, acc.w);
    }
    for (; i < e; ++i) {
        int col = __ldg(ecol + i);
        float w = __ldg(evals + i);
        float4 v = __ldg(vcur + (size_t)col * 16 + ch);
        acc.x = fmaf(w, v.x, acc.x);
        acc.y = fmaf(w, v.y, acc.y);
        acc.z = fmaf(w, v.z, acc.z);
        acc.w = fmaf(w, v.w, acc.w);
    }

    size_t o = (size_t)row * 16 + ch;
    float4* vnext = (float4*)g_tb[nxt];
    float4* z4 = (float4*)z;

    if (first) {
        float g0 = gamma[0], g1 = gamma[1];
        float4 h = vcur[o];
        vnext[o] = acc;
        float4 zz;
        zz.x = g0 * h.x + g1 * acc.x;
        zz.y = g0 * h.y + g1 * acc.y;
        zz.z = g0 * h.z + g1 * acc.z;
        zz.w = g0 * h.w + g1 * acc.w;
        z4[o] = zz;
    } else {
        const float4* vprev = (const float4*)g_tb[prev];
        float4 p = vprev[o];
        float4 tn;
        tn.x = 2.f * acc.x - p.x;
        tn.y = 2.f * acc.y - p.y;
        tn.z = 2.f * acc.z - p.z;
        tn.w = 2.f * acc.w - p.w;
        if (!last) vnext[o] = tn;
        float g = gamma[k];
        float4 zz = z4[o];
        zz.x = fmaf(g, tn.x, zz.x);
        zz.y = fmaf(g, tn.y, zz.y);
        zz.z = fmaf(g, tn.z, zz.z);
        zz.w = fmaf(g, tn.w, zz.w);
        z4[o] = zz;
    }
}

// ---------------- launch ----------------------------------------------------
extern "C" void kernel_launch(void* const* d_in, const int* in_sizes, int n_in,
                              void* d_out, int out_size) {
    const float* x     = (const float*)d_in[0];
    const int*   erow  = (const int*)d_in[1];
    const int*   ecol  = (const int*)d_in[2];
    const float* evals = (const float*)d_in[3];
    const float* W1    = (const float*)d_in[4];
    const float* b1    = (const float*)d_in[5];
    const float* W2    = (const float*)d_in[6];
    const float* b2    = (const float*)d_in[7];
    const float* gamma = (const float*)d_in[8];
    float* z = (float*)d_out;

    float *tb0;
    __nv_bfloat16 *ahi, *alo, *hhi, *hlo, *w1hi, *w1lo, *w2hi, *w2lo;
    cudaGetSymbolAddress((void**)&tb0, g_tb);
    cudaGetSymbolAddress((void**)&ahi, g_ahi);
    cudaGetSymbolAddress((void**)&alo, g_alo);
    cudaGetSymbolAddress((void**)&hhi, g_hhi);
    cudaGetSymbolAddress((void**)&hlo, g_hlo);
    cudaGetSymbolAddress((void**)&w1hi, g_w1hi);
    cudaGetSymbolAddress((void**)&w1lo, g_w1lo);
    cudaGetSymbolAddress((void**)&w2hi, g_w2hi);
    cudaGetSymbolAddress((void**)&w2lo, g_w2lo);

    // dynamic smem: 1024 + 2 * (32768 + 2*64*128) = 99328 -> 2 CTAs/SM
    constexpr int SMEMG = 1024 + 2 * (32768 + 2 * 64 * 128);
    cudaFuncSetAttribute(tc_gemm<64, 8, 4, 2, true>,
                         cudaFuncAttributeMaxDynamicSharedMemorySize, SMEMG);
    cudaFuncSetAttribute(tc_gemm<64, 4, 4, 2, false>,
                         cudaFuncAttributeMaxDynamicSharedMemorySize, SMEMG);

    const int MTILES = (NN + 127) / 128;  // 782

    prep_w<8><<<(IND * HID + 255) / 256, 256>>>(W1, IND, w1hi, w1lo);
    prep_w<6><<<(HID * NC + 255) / 256, 256>>>(W2, HID, w2hi, w2lo);

    {
        long long tot = (long long)NN * (IND / 8);
        prep_a<9><<<(unsigned)((tot + 255) / 256), 256>>>(x, ahi, alo);
    }
    // GEMM1: relu(x@W1 + b1) -> split bf16 planes (g_hhi/g_hlo)
    {
        dim3 grid(4, MTILES);   // 4 n-tiles of 64, adjacent CTAs share A tile
        tc_gemm<64, 8, 4, 2, true><<<grid, 256, SMEMG>>>(
            ahi, alo, w1hi, w1lo, b1, nullptr, hhi, hlo, HID);
    }
    // GEMM2: h@W2 + b2 -> g_tb[0] fp32
    {
        dim3 grid(1, MTILES);
        tc_gemm<64, 4, 4, 2, false><<<grid, 256, SMEMG>>>(
            hhi, hlo, w2hi, w2lo, b2, tb0, nullptr, nullptr, NC);
    }

    build_row_ptr<<<(NN + 256) / 256, 256>>>(erow);

    const int SPMM_BLOCKS = (NN * 16 + 255) / 256;
    spmm_cheb<<<SPMM_BLOCKS, 256>>>(ecol, evals, gamma, z, 0, 0, 1, 1, 1, 0);
    int p = 0, c = 1;
    for (int k = 2; k <= 8; ++k) {
        int n = 3 - p - c;
        spmm_cheb<<<SPMM_BLOCKS, 256>>>(ecol, evals, gamma, z, c, p, n, k, 0, k == 8);
        p = c; c = n;
    }
}

// round 13
// speedup vs baseline: 1.4024x; 1.4024x over previous
#include <cuda_runtime.h>
#include <cuda_bf16.h>
#include <cstdint>

#define NN 100000
#define ROWSP 100096           // NN padded to multiple of 128
#define NE 3200000
#define IND 512
#define HID 256
#define NC  64

// ---------------- scratch (static device globals; no runtime allocation) ----
__device__ float g_tb[3][(size_t)NN * NC];                     // rotating T_k buffers
__device__ int   g_rp[NN + 1];                                 // CSR row_ptr
__device__ __align__(128) __nv_bfloat16 g_ahi[(size_t)8 * ROWSP * 64];
__device__ __align__(128) __nv_bfloat16 g_alo[(size_t)8 * ROWSP * 64];
__device__ __align__(128) __nv_bfloat16 g_hhi[(size_t)4 * ROWSP * 64];
__device__ __align__(128) __nv_bfloat16 g_hlo[(size_t)4 * ROWSP * 64];
__device__ __align__(128) __nv_bfloat16 g_w1hi[8 * 256 * 64], g_w1lo[8 * 256 * 64];
__device__ __align__(128) __nv_bfloat16 g_w2hi[4 * 64 * 64],  g_w2lo[4 * 64 * 64];

// ---------------- inline PTX helpers (base ISA only) ------------------------
__device__ __forceinline__ uint32_t smem_u32(const void* p) {
    uint32_t a;
    asm("{ .reg .u64 t; cvta.to.shared.u64 t, %1; cvt.u32.u64 %0, t; }" : "=r"(a) : "l"(p));
    return a;
}
#define MBARRIER_INIT(addr, cnt) \
    asm volatile("mbarrier.init.shared.b64 [%0], %1;" :: "r"(addr), "r"((uint32_t)(cnt)) : "memory")
#define MBARRIER_INVAL(addr) \
    asm volatile("mbarrier.inval.shared.b64 [%0];" :: "r"(addr) : "memory")
#define MBARRIER_EXPECT_TX(addr, bytes) \
    asm volatile("mbarrier.arrive.expect_tx.shared.b64 _, [%0], %1;" :: "r"(addr), "r"((uint32_t)(bytes)) : "memory")
__device__ __forceinline__ void mbar_wait(uint32_t mbar, uint32_t parity) {
    asm volatile(
        "{\n\t.reg .pred P1;\n\t"
        "WAIT_LOOP_%=:\n\t"
        "mbarrier.try_wait.parity.acquire.cta.shared::cta.b64 P1, [%0], %1, 0x989680;\n\t"
        "@P1 bra.uni WAIT_DONE_%=;\n\t"
        "bra.uni WAIT_LOOP_%=;\n\t"
        "WAIT_DONE_%=:\n\t}"
        :: "r"(mbar), "r"(parity) : "memory");
}
#define BULK_G2S(dst, src, bytes, mbar) \
    asm volatile("cp.async.bulk.shared::cta.global.mbarrier::complete_tx::bytes [%0], [%1], %2, [%3];" \
        :: "r"((uint32_t)(dst)), "l"(src), "r"((uint32_t)(bytes)), "r"((uint32_t)(mbar)) : "memory")

__device__ __forceinline__ void ldsm4(uint32_t* r, uint32_t addr) {
    asm volatile("ldmatrix.sync.aligned.m8n8.x4.shared.b16 {%0,%1,%2,%3}, [%4];"
        : "=r"(r[0]), "=r"(r[1]), "=r"(r[2]), "=r"(r[3]) : "r"(addr));
}
__device__ __forceinline__ void mma_bf16(float* d, const uint32_t* a, const uint32_t* b) {
    asm volatile("mma.sync.aligned.m16n8k16.row.col.f32.bf16.bf16.f32 "
        "{%0,%1,%2,%3}, {%4,%5,%6,%7}, {%8,%9}, {%0,%1,%2,%3};"
        : "+f"(d[0]), "+f"(d[1]), "+f"(d[2]), "+f"(d[3])
        : "r"(a[0]), "r"(a[1]), "r"(a[2]), "r"(a[3]), "r"(b[0]), "r"(b[1]));
}

// ---------------- prep kernels ----------------------------------------------
template <int KSHIFT>
__global__ void prep_a(const float* __restrict__ src,
                       __nv_bfloat16* __restrict__ dhi, __nv_bfloat16* __restrict__ dlo) {
    constexpr int K = 1 << KSHIFT;
    constexpr int G = K / 8;
    long long idx = (long long)blockIdx.x * blockDim.x + threadIdx.x;
    if (idx >= (long long)NN * G) return;
    int r = (int)(idx / G);
    int g = (int)(idx % G);
    int k = g * 8;
    int c = k >> 6, kk = k & 63;

    const float4* s4 = (const float4*)(src + (size_t)r * K + k);
    float4 v0 = s4[0], v1 = s4[1];
    float f[8] = {v0.x, v0.y, v0.z, v0.w, v1.x, v1.y, v1.z, v1.w};
    __nv_bfloat162 hi[4], lo[4];
#pragma unroll
    for (int i = 0; i < 4; ++i) {
        __nv_bfloat16 h0 = __float2bfloat16(f[2 * i]);
        __nv_bfloat16 h1 = __float2bfloat16(f[2 * i + 1]);
        hi[i] = __nv_bfloat162(h0, h1);
        lo[i] = __nv_bfloat162(__float2bfloat16(f[2 * i] - __bfloat162float(h0)),
                               __float2bfloat16(f[2 * i + 1] - __bfloat162float(h1)));
    }
    uint32_t off = (uint32_t)r * 128 + (((uint32_t)kk * 2) ^ (((uint32_t)r & 7) << 4));
    size_t pbase = (size_t)c * ROWSP * 128;
    *(uint4*)((char*)dhi + pbase + off) = *(uint4*)hi;
    *(uint4*)((char*)dlo + pbase + off) = *(uint4*)lo;
}

template <int NSHIFT>
__global__ void prep_w(const float* __restrict__ src, int K,
                       __nv_bfloat16* __restrict__ dhi, __nv_bfloat16* __restrict__ dlo) {
    constexpr int N = 1 << NSHIFT;
    int idx = blockIdx.x * blockDim.x + threadIdx.x;
    if (idx >= K * N) return;
    int k = idx >> NSHIFT;
    int n = idx & (N - 1);
    int c = k >> 6, kk = k & 63;
    float v = src[idx];
    __nv_bfloat16 hi = __float2bfloat16(v);
    __nv_bfloat16 lo = __float2bfloat16(v - __bfloat162float(hi));
    int poff = (kk << 1) ^ ((n & 7) << 4);
    size_t dst = ((size_t)c * N + n) * 64 + (poff >> 1);
    dhi[dst] = hi;
    dlo[dst] = lo;
}

// ---------------- split-bf16 mma.sync GEMM ----------------------------------
// D[128, BN] = A[128, K] @ B[BN, K]^T; 3 split products per 64-chunk.
// BN=64, 2-stage, 99328 B smem -> 2 CTAs/SM (R12-measured best: tensor 70.3%).
template <int BN, int NCHUNK, int WM, int WN, bool SPLIT_OUT>
__global__ void __launch_bounds__(256, 2)
tc_gemm(const __nv_bfloat16* __restrict__ Ahi, const __nv_bfloat16* __restrict__ Alo,
        const __nv_bfloat16* __restrict__ Bhi, const __nv_bfloat16* __restrict__ Blo,
        const float* __restrict__ bias, float* __restrict__ C,
        __nv_bfloat16* __restrict__ Ohi, __nv_bfloat16* __restrict__ Olo, int NB) {
    constexpr int WR = 128 / WM;
    constexpr int WC = BN / WN;
    constexpr int MT = WR / 16;
    constexpr int NT = WC / 8;
    constexpr uint32_t BNB = BN * 128;
    constexpr uint32_t BUFB = 32768 + 2 * BNB;

    extern __shared__ char smem[];
    const uint32_t sb = smem_u32(smem);
    const int tid = threadIdx.x;
    const int lane = tid & 31;
    const int wid = tid >> 5;
    const int wm = wid / WN, wn = wid % WN;
    const int bm = blockIdx.y * 128;
    const int n0 = blockIdx.x * BN;            // n fast: CTAs share A tile in L2

    const uint32_t mb0 = sb + 8, mb1 = sb + 24;
    if (tid == 0) { MBARRIER_INIT(mb0, 1); MBARRIER_INIT(mb1, 1); }
    __syncthreads();

    auto issue = [&](int c) {
        int buf = c & 1;
        uint32_t mb = buf ? mb1 : mb0;
        uint32_t base = sb + 1024 + (uint32_t)buf * BUFB;
        MBARRIER_EXPECT_TX(mb, BUFB);
        const char* ah = (const char*)Ahi + ((size_t)c * ROWSP + bm) * 128;
        const char* al = (const char*)Alo + ((size_t)c * ROWSP + bm) * 128;
        const char* bh = (const char*)Bhi + ((size_t)c * NB + n0) * 128;
        const char* bl = (const char*)Blo + ((size_t)c * NB + n0) * 128;
        BULK_G2S(base,               ah, 16384, mb);
        BULK_G2S(base + 16384,       al, 16384, mb);
        BULK_G2S(base + 32768,       bh, BNB,   mb);
        BULK_G2S(base + 32768 + BNB, bl, BNB,   mb);
    };
    if (tid == 0) {
#pragma unroll
        for (int c = 0; c < 2 && c < NCHUNK; ++c) issue(c);
    }

    const int arow = lane & 15;
    const int akb = (lane >> 4) << 3;
    const uint32_t aRowOff = (uint32_t)(wm * WR + arow) * 128;
    const uint32_t aSw = (uint32_t)(arow & 7) << 4;
    const int brow = (lane & 7) + ((lane >> 4) << 3);
    const int bkb = ((lane >> 3) & 1) << 3;
    const uint32_t bRowOff = (uint32_t)(wn * WC + brow) * 128;
    const uint32_t bSw = (uint32_t)(brow & 7) << 4;

    float acc[MT][NT][4];
#pragma unroll
    for (int i = 0; i < MT; ++i)
#pragma unroll
        for (int j = 0; j < NT; ++j)
#pragma unroll
            for (int q = 0; q < 4; ++q) acc[i][j][q] = 0.f;

    for (int c = 0; c < NCHUNK; ++c) {
        const int buf = c & 1;
        mbar_wait(buf ? mb1 : mb0, (uint32_t)(c >> 1) & 1);

        const uint32_t base = sb + 1024 + (uint32_t)buf * BUFB;
        const uint32_t aHiS = base, aLoS = base + 16384;
        const uint32_t bHiS = base + 32768, bLoS = base + 32768 + BNB;

#pragma unroll
        for (int ks = 0; ks < 4; ++ks) {
            uint32_t ah[MT][4], al[MT][4], bh[NT][2], bl[NT][2];
            const uint32_t akByte = ((uint32_t)((ks * 16 + akb) * 2)) ^ aSw;
#pragma unroll
            for (int mt = 0; mt < MT; ++mt) {
                uint32_t o = aRowOff + (uint32_t)mt * 2048 + akByte;
                ldsm4(ah[mt], aHiS + o);
                ldsm4(al[mt], aLoS + o);
            }
            const uint32_t bkByte = ((uint32_t)((ks * 16 + bkb) * 2)) ^ bSw;
#pragma unroll
            for (int p = 0; p < NT / 2; ++p) {
                uint32_t o = bRowOff + (uint32_t)p * 2048 + bkByte;
                uint32_t t[4];
                ldsm4(t, bHiS + o);
                bh[2 * p][0] = t[0]; bh[2 * p][1] = t[1];
                bh[2 * p + 1][0] = t[2]; bh[2 * p + 1][1] = t[3];
                ldsm4(t, bLoS + o);
                bl[2 * p][0] = t[0]; bl[2 * p][1] = t[1];
                bl[2 * p + 1][0] = t[2]; bl[2 * p + 1][1] = t[3];
            }
#pragma unroll
            for (int mt = 0; mt < MT; ++mt)
#pragma unroll
                for (int nt = 0; nt < NT; ++nt)
                    mma_bf16(acc[mt][nt], ah[mt], bh[nt]);
#pragma unroll
            for (int mt = 0; mt < MT; ++mt)
#pragma unroll
                for (int nt = 0; nt < NT; ++nt)
                    mma_bf16(acc[mt][nt], ah[mt], bl[nt]);
#pragma unroll
            for (int mt = 0; mt < MT; ++mt)
#pragma unroll
                for (int nt = 0; nt < NT; ++nt)
                    mma_bf16(acc[mt][nt], al[mt], bh[nt]);
        }
        __syncthreads();
        if (tid == 0 && c + 2 < NCHUNK) issue(c + 2);
    }

    // epilogue
    const int r0 = bm + wm * WR + (lane >> 2);
#pragma unroll
    for (int mt = 0; mt < MT; ++mt) {
#pragma unroll
        for (int nt = 0; nt < NT; ++nt) {
            int row = r0 + mt * 16;
            int col = n0 + wn * WC + nt * 8 + (lane & 3) * 2;
            float bv0 = __ldg(bias + col), bv1 = __ldg(bias + col + 1);
            if (SPLIT_OUT) {
                int pl = col >> 6, kk = col & 63;
                size_t pbase = (size_t)pl * ROWSP * 128;
                uint32_t xoff = ((uint32_t)kk * 2);
#pragma unroll
                for (int half = 0; half < 2; ++half) {
                    int r = row + half * 8;
                    if (r >= NN) continue;
                    float v0 = fmaxf(acc[mt][nt][2 * half + 0] + bv0, 0.f);
                    float v1 = fmaxf(acc[mt][nt][2 * half + 1] + bv1, 0.f);
                    __nv_bfloat16 h0 = __float2bfloat16(v0);
                    __nv_bfloat16 h1 = __float2bfloat16(v1);
                    __nv_bfloat162 hv(h0, h1);
                    __nv_bfloat162 lv(__float2bfloat16(v0 - __bfloat162float(h0)),
                                      __float2bfloat16(v1 - __bfloat162float(h1)));
                    uint32_t off = (uint32_t)r * 128 + (xoff ^ (((uint32_t)r & 7) << 4));
                    *(__nv_bfloat162*)((char*)Ohi + pbase + off) = hv;
                    *(__nv_bfloat162*)((char*)Olo + pbase + off) = lv;
                }
            } else {
#pragma unroll
                for (int half = 0; half < 2; ++half) {
                    int r = row + half * 8;
                    if (r >= NN) continue;
                    float2 v;
                    v.x = acc[mt][nt][2 * half + 0] + bv0;
                    v.y = acc[mt][nt][2 * half + 1] + bv1;
                    *(float2*)&C[(size_t)r * NB + col] = v;
                }
            }
        }
    }
    __syncthreads();
    if (tid == 0) { MBARRIER_INVAL(mb0); MBARRIER_INVAL(mb1); }
}

// ---------------- row_ptr build ---------------------------------------------
__global__ void build_row_ptr(const int* __restrict__ erow) {
    int r = blockIdx.x * blockDim.x + threadIdx.x;
    if (r > NN) return;
    int lo = 0, hi = NE;
    while (lo < hi) {
        int mid = (lo + hi) >> 1;
        if (erow[mid] < r) lo = mid + 1; else hi = mid;
    }
    g_rp[r] = lo;
}

// ---------------- fused CSR SpMM + Chebyshev recurrence ---------------------
// 16 thr/row; edge index/value loads vectorized (int4/float4, 16B-aligned
// main loop with scalar head/tail) -> LDG instructions per 4 edges: 12 -> 6.
__global__ void spmm_cheb(const int* __restrict__ ecol, const float* __restrict__ evals,
                          const float* __restrict__ gamma, float* __restrict__ z,
                          int cur, int prev, int nxt, int k, int first, int last) {
    int t = blockIdx.x * blockDim.x + threadIdx.x;
    int row = t >> 4;
    int ch = t & 15;
    if (row >= NN) return;

    const float4* vcur = (const float4*)g_tb[cur];
    int s = g_rp[row];
    int e = g_rp[row + 1];

    float4 acc = make_float4(0.f, 0.f, 0.f, 0.f);
    int i = s;
    int head = (s + 3) & ~3;
    if (head > e) head = e;
    for (; i < head; ++i) {
        int col = __ldg(ecol + i);
        float w = __ldg(evals + i);
        float4 v = __ldg(vcur + (size_t)col * 16 + ch);
        acc.x = fmaf(w, v.x, acc.x);
        acc.y = fmaf(w, v.y, acc.y);
        acc.z = fmaf(w, v.z, acc.z);
        acc.w = fmaf(w, v.w, acc.w);
    }
    for (; i + 4 <= e; i += 4) {
        int4 cc = __ldg((const int4*)(ecol + i));
        float4 ww = __ldg((const float4*)(evals + i));
        float4 v0 = __ldg(vcur + (size_t)cc.x * 16 + ch);
        float4 v1 = __ldg(vcur + (size_t)cc.y * 16 + ch);
        float4 v2 = __ldg(vcur + (size_t)cc.z * 16 + ch);
        float4 v3 = __ldg(vcur + (size_t)cc.w * 16 + ch);
        acc.x = fmaf(ww.x, v0.x, acc.x); acc.y = fmaf(ww.x, v0.y, acc.y);
        acc.z = fmaf(ww.x, v0.z, acc.z); acc.w = fmaf(ww.x, v0.w, acc.w);
        acc.x = fmaf(ww.y, v1.x, acc.x); acc.y = fmaf(ww.y, v1.y, acc.y);
        acc.z = fmaf(ww.y, v1.z, acc.z); acc.w = fmaf(ww.y, v1.w, acc.w);
        acc.x = fmaf(ww.z, v2.x, acc.x); acc.y = fmaf(ww.z, v2.y, acc.y);
        acc.z = fmaf(ww.z, v2.z, acc.z); acc.w = fmaf(ww.z, v2.w, acc.w);
        acc.x = fmaf(ww.w, v3.x, acc.x); acc.y = fmaf(ww.w, v3.y, acc.y);
        acc.z = fmaf(ww.w, v3.z, acc.z); acc.w = fmaf(ww.w, v3.w, acc.w);
    }
    for (; i < e; ++i) {
        int col = __ldg(ecol + i);
        float w = __ldg(evals + i);
        float4 v = __ldg(vcur + (size_t)col * 16 + ch);
        acc.x = fmaf(w, v.x, acc.x);
        acc.y = fmaf(w, v.y, acc.y);
        acc.z = fmaf(w, v.z, acc.z);
        acc.w = fmaf(w, v.w, acc.w);
    }

    size_t o = (size_t)row * 16 + ch;
    float4* vnext = (float4*)g_tb[nxt];
    float4* z4 = (float4*)z;

    if (first) {
        float g0 = gamma[0], g1 = gamma[1];
        float4 h = vcur[o];
        vnext[o] = acc;
        float4 zz;
        zz.x = g0 * h.x + g1 * acc.x;
        zz.y = g0 * h.y + g1 * acc.y;
        zz.z = g0 * h.z + g1 * acc.z;
        zz.w = g0 * h.w + g1 * acc.w;
        z4[o] = zz;
    } else {
        const float4* vprev = (const float4*)g_tb[prev];
        float4 p = vprev[o];
        float4 tn;
        tn.x = 2.f * acc.x - p.x;
        tn.y = 2.f * acc.y - p.y;
        tn.z = 2.f * acc.z - p.z;
        tn.w = 2.f * acc.w - p.w;
        if (!last) vnext[o] = tn;
        float g = gamma[k];
        float4 zz = z4[o];
        zz.x = fmaf(g, tn.x, zz.x);
        zz.y = fmaf(g, tn.y, zz.y);
        zz.z = fmaf(g, tn.z, zz.z);
        zz.w = fmaf(g, tn.w, zz.w);
        z4[o] = zz;
    }
}

// ---------------- launch ----------------------------------------------------
extern "C" void kernel_launch(void* const* d_in, const int* in_sizes, int n_in,
                              void* d_out, int out_size) {
    const float* x     = (const float*)d_in[0];
    const int*   erow  = (const int*)d_in[1];
    const int*   ecol  = (const int*)d_in[2];
    const float* evals = (const float*)d_in[3];
    const float* W1    = (const float*)d_in[4];
    const float* b1    = (const float*)d_in[5];
    const float* W2    = (const float*)d_in[6];
    const float* b2    = (const float*)d_in[7];
    const float* gamma = (const float*)d_in[8];
    float* z = (float*)d_out;

    float *tb0;
    __nv_bfloat16 *ahi, *alo, *hhi, *hlo, *w1hi, *w1lo, *w2hi, *w2lo;
    cudaGetSymbolAddress((void**)&tb0, g_tb);
    cudaGetSymbolAddress((void**)&ahi, g_ahi);
    cudaGetSymbolAddress((void**)&alo, g_alo);
    cudaGetSymbolAddress((void**)&hhi, g_hhi);
    cudaGetSymbolAddress((void**)&hlo, g_hlo);
    cudaGetSymbolAddress((void**)&w1hi, g_w1hi);
    cudaGetSymbolAddress((void**)&w1lo, g_w1lo);
    cudaGetSymbolAddress((void**)&w2hi, g_w2hi);
    cudaGetSymbolAddress((void**)&w2lo, g_w2lo);

    // dynamic smem: 1024 + 2 * (32768 + 2*64*128) = 99328 -> 2 CTAs/SM
    constexpr int SMEMG = 1024 + 2 * (32768 + 2 * 64 * 128);
    cudaFuncSetAttribute(tc_gemm<64, 8, 4, 2, true>,
                         cudaFuncAttributeMaxDynamicSharedMemorySize, SMEMG);
    cudaFuncSetAttribute(tc_gemm<64, 4, 4, 2, false>,
                         cudaFuncAttributeMaxDynamicSharedMemorySize, SMEMG);

    const int MTILES = (NN + 127) / 128;  // 782

    prep_w<8><<<(IND * HID + 255) / 256, 256>>>(W1, IND, w1hi, w1lo);
    prep_w<6><<<(HID * NC + 255) / 256, 256>>>(W2, HID, w2hi, w2lo);

    {
        long long tot = (long long)NN * (IND / 8);
        prep_a<9><<<(unsigned)((tot + 255) / 256), 256>>>(x, ahi, alo);
    }
    // GEMM1: relu(x@W1 + b1) -> split bf16 planes (g_hhi/g_hlo)
    {
        dim3 grid(4, MTILES);
        tc_gemm<64, 8, 4, 2, true><<<grid, 256, SMEMG>>>(
            ahi, alo, w1hi, w1lo, b1, nullptr, hhi, hlo, HID);
    }
    // GEMM2: h@W2 + b2 -> g_tb[0] fp32
    {
        dim3 grid(1, MTILES);
        tc_gemm<64, 4, 4, 2, false><<<grid, 256, SMEMG>>>(
            hhi, hlo, w2hi, w2lo, b2, tb0, nullptr, nullptr, NC);
    }

    build_row_ptr<<<(NN + 256) / 256, 256>>>(erow);

    const int SPMM_BLOCKS = (NN * 16 + 255) / 256;
    spmm_cheb<<<SPMM_BLOCKS, 256>>>(ecol, evals, gamma, z, 0, 0, 1, 1, 1, 0);
    int p = 0, c = 1;
    for (int k = 2; k <= 8; ++k) {
        int n = 3 - p - c;
        spmm_cheb<<<SPMM_BLOCKS, 256>>>(ecol, evals, gamma, z, c, p, n, k, 0, k == 8);
        p = c; c = n;
    }
}

// round 15
// speedup vs baseline: 1.5134x; 1.0792x over previous
#include <cuda_runtime.h>
#include <cuda_fp16.h>
#include <cstdint>

#define NN 100000
#define ROWSP 100096           // NN padded to multiple of 128
#define NE 3200000
#define IND 512
#define HID 256
#define NC  64

// ---------------- scratch (static device globals; no runtime allocation) ----
__device__ float g_tb[3][(size_t)NN * NC];                     // rotating T_k buffers
__device__ int   g_rp[NN + 1];                                 // CSR row_ptr
// A operand planes: [K/64][ROWSP][64] fp16, SW128-swizzled per 128B row
__device__ __align__(128) __half g_ahi[(size_t)8 * ROWSP * 64];
__device__ __align__(128) __half g_alo[(size_t)8 * ROWSP * 64];
__device__ __align__(128) __half g_hhi[(size_t)4 * ROWSP * 64];
__device__ __align__(128) __half g_hlo[(size_t)4 * ROWSP * 64];
// W operands single fp16 plane (B error ~0.5*eps_fp16 ~ 2.4e-4, under gate)
__device__ __align__(128) __half g_w1[8 * 256 * 64];
__device__ __align__(128) __half g_w2[4 * 64 * 64];

// ---------------- inline PTX helpers (base ISA only) ------------------------
__device__ __forceinline__ uint32_t smem_u32(const void* p) {
    uint32_t a;
    asm("{ .reg .u64 t; cvta.to.shared.u64 t, %1; cvt.u32.u64 %0, t; }" : "=r"(a) : "l"(p));
    return a;
}
#define MBARRIER_INIT(addr, cnt) \
    asm volatile("mbarrier.init.shared.b64 [%0], %1;" :: "r"(addr), "r"((uint32_t)(cnt)) : "memory")
#define MBARRIER_INVAL(addr) \
    asm volatile("mbarrier.inval.shared.b64 [%0];" :: "r"(addr) : "memory")
#define MBARRIER_EXPECT_TX(addr, bytes) \
    asm volatile("mbarrier.arrive.expect_tx.shared.b64 _, [%0], %1;" :: "r"(addr), "r"((uint32_t)(bytes)) : "memory")
__device__ __forceinline__ void mbar_wait(uint32_t mbar, uint32_t parity) {
    asm volatile(
        "{\n\t.reg .pred P1;\n\t"
        "WAIT_LOOP_%=:\n\t"
        "mbarrier.try_wait.parity.acquire.cta.shared::cta.b64 P1, [%0], %1, 0x989680;\n\t"
        "@P1 bra.uni WAIT_DONE_%=;\n\t"
        "bra.uni WAIT_LOOP_%=;\n\t"
        "WAIT_DONE_%=:\n\t}"
        :: "r"(mbar), "r"(parity) : "memory");
}
#define BULK_G2S(dst, src, bytes, mbar) \
    asm volatile("cp.async.bulk.shared::cta.global.mbarrier::complete_tx::bytes [%0], [%1], %2, [%3];" \
        :: "r"((uint32_t)(dst)), "l"(src), "r"((uint32_t)(bytes)), "r"((uint32_t)(mbar)) : "memory")

__device__ __forceinline__ void ldsm4(uint32_t* r, uint32_t addr) {
    asm volatile("ldmatrix.sync.aligned.m8n8.x4.shared.b16 {%0,%1,%2,%3}, [%4];"
        : "=r"(r[0]), "=r"(r[1]), "=r"(r[2]), "=r"(r[3]) : "r"(addr));
}
__device__ __forceinline__ void mma_f16(float* d, const uint32_t* a, const uint32_t* b) {
    asm volatile("mma.sync.aligned.m16n8k16.row.col.f32.f16.f16.f32 "
        "{%0,%1,%2,%3}, {%4,%5,%6,%7}, {%8,%9}, {%0,%1,%2,%3};"
        : "+f"(d[0]), "+f"(d[1]), "+f"(d[2]), "+f"(d[3])
        : "r"(a[0]), "r"(a[1]), "r"(a[2]), "r"(a[3]), "r"(b[0]), "r"(b[1]));
}

// ---------------- prep kernels ----------------------------------------------
template <int KSHIFT>
__global__ void prep_a(const float* __restrict__ src,
                       __half* __restrict__ dhi, __half* __restrict__ dlo) {
    constexpr int K = 1 << KSHIFT;
    constexpr int G = K / 8;
    long long idx = (long long)blockIdx.x * blockDim.x + threadIdx.x;
    if (idx >= (long long)NN * G) return;
    int r = (int)(idx / G);
    int g = (int)(idx % G);
    int k = g * 8;
    int c = k >> 6, kk = k & 63;

    const float4* s4 = (const float4*)(src + (size_t)r * K + k);
    float4 v0 = s4[0], v1 = s4[1];
    float f[8] = {v0.x, v0.y, v0.z, v0.w, v1.x, v1.y, v1.z, v1.w};
    __half2 hi[4], lo[4];
#pragma unroll
    for (int i = 0; i < 4; ++i) {
        __half h0 = __float2half_rn(f[2 * i]);
        __half h1 = __float2half_rn(f[2 * i + 1]);
        hi[i] = __half2(h0, h1);
        lo[i] = __half2(__float2half_rn(f[2 * i] - __half2float(h0)),
                        __float2half_rn(f[2 * i + 1] - __half2float(h1)));
    }
    uint32_t off = (uint32_t)r * 128 + (((uint32_t)kk * 2) ^ (((uint32_t)r & 7) << 4));
    size_t pbase = (size_t)c * ROWSP * 128;
    *(uint4*)((char*)dhi + pbase + off) = *(uint4*)hi;
    *(uint4*)((char*)dlo + pbase + off) = *(uint4*)lo;
}

template <int NSHIFT>
__global__ void prep_w(const float* __restrict__ src, int K, __half* __restrict__ dst) {
    constexpr int N = 1 << NSHIFT;
    int idx = blockIdx.x * blockDim.x + threadIdx.x;
    if (idx >= K * N) return;
    int k = idx >> NSHIFT;
    int n = idx & (N - 1);
    int c = k >> 6, kk = k & 63;
    int poff = (kk << 1) ^ ((n & 7) << 4);
    size_t d = ((size_t)c * N + n) * 64 + (poff >> 1);
    dst[d] = __float2half_rn(src[idx]);
}

// ---------------- fp16 A-split mma.sync GEMM --------------------------------
// D[128, BN] = A[128, K] @ B[BN, K]^T; A = Ahi + Alo (fp16), B single fp16.
// 2 MMA products per chunk. BN=64, 2-stage, 82944 B smem -> 2 CTAs/SM.
template <int BN, int NCHUNK, int WM, int WN, bool SPLIT_OUT>
__global__ void __launch_bounds__(256, 2)
tc_gemm(const __half* __restrict__ Ahi, const __half* __restrict__ Alo,
        const __half* __restrict__ B,
        const float* __restrict__ bias, float* __restrict__ C,
        __half* __restrict__ Ohi, __half* __restrict__ Olo, int NB) {
    constexpr int WR = 128 / WM;
    constexpr int WC = BN / WN;
    constexpr int MT = WR / 16;
    constexpr int NT = WC / 8;
    constexpr uint32_t BNB = BN * 128;
    constexpr uint32_t BUFB = 32768 + BNB;

    extern __shared__ char smem[];
    const uint32_t sb = smem_u32(smem);
    const int tid = threadIdx.x;
    const int lane = tid & 31;
    const int wid = tid >> 5;
    const int wm = wid / WN, wn = wid % WN;
    const int bm = blockIdx.y * 128;
    const int n0 = blockIdx.x * BN;            // n fast: CTAs share A tile in L2

    const uint32_t mb0 = sb + 8, mb1 = sb + 24;
    if (tid == 0) { MBARRIER_INIT(mb0, 1); MBARRIER_INIT(mb1, 1); }
    __syncthreads();

    auto issue = [&](int c) {
        int buf = c & 1;
        uint32_t mb = buf ? mb1 : mb0;
        uint32_t base = sb + 1024 + (uint32_t)buf * BUFB;
        MBARRIER_EXPECT_TX(mb, BUFB);
        const char* ah = (const char*)Ahi + ((size_t)c * ROWSP + bm) * 128;
        const char* al = (const char*)Alo + ((size_t)c * ROWSP + bm) * 128;
        const char* bp = (const char*)B + ((size_t)c * NB + n0) * 128;
        BULK_G2S(base,         ah, 16384, mb);
        BULK_G2S(base + 16384, al, 16384, mb);
        BULK_G2S(base + 32768, bp, BNB,   mb);
    };
    if (tid == 0) {
#pragma unroll
        for (int c = 0; c < 2 && c < NCHUNK; ++c) issue(c);
    }

    const int arow = lane & 15;
    const int akb = (lane >> 4) << 3;
    const uint32_t aRowOff = (uint32_t)(wm * WR + arow) * 128;
    const uint32_t aSw = (uint32_t)(arow & 7) << 4;
    const int brow = (lane & 7) + ((lane >> 4) << 3);
    const int bkb = ((lane >> 3) & 1) << 3;
    const uint32_t bRowOff = (uint32_t)(wn * WC + brow) * 128;
    const uint32_t bSw = (uint32_t)(brow & 7) << 4;

    float acc[MT][NT][4];
#pragma unroll
    for (int i = 0; i < MT; ++i)
#pragma unroll
        for (int j = 0; j < NT; ++j)
#pragma unroll
            for (int q = 0; q < 4; ++q) acc[i][j][q] = 0.f;

    for (int c = 0; c < NCHUNK; ++c) {
        const int buf = c & 1;
        mbar_wait(buf ? mb1 : mb0, (uint32_t)(c >> 1) & 1);

        const uint32_t base = sb + 1024 + (uint32_t)buf * BUFB;
        const uint32_t aHiS = base, aLoS = base + 16384;
        const uint32_t bS = base + 32768;

#pragma unroll
        for (int ks = 0; ks < 4; ++ks) {
            uint32_t ah[MT][4], al[MT][4], bh[NT][2];
            const uint32_t akByte = ((uint32_t)((ks * 16 + akb) * 2)) ^ aSw;
#pragma unroll
            for (int mt = 0; mt < MT; ++mt) {
                uint32_t o = aRowOff + (uint32_t)mt * 2048 + akByte;
                ldsm4(ah[mt], aHiS + o);
                ldsm4(al[mt], aLoS + o);
            }
            const uint32_t bkByte = ((uint32_t)((ks * 16 + bkb) * 2)) ^ bSw;
#pragma unroll
            for (int p = 0; p < NT / 2; ++p) {
                uint32_t o = bRowOff + (uint32_t)p * 2048 + bkByte;
                uint32_t t[4];
                ldsm4(t, bS + o);
                bh[2 * p][0] = t[0]; bh[2 * p][1] = t[1];
                bh[2 * p + 1][0] = t[2]; bh[2 * p + 1][1] = t[3];
            }
#pragma unroll
            for (int mt = 0; mt < MT; ++mt)
#pragma unroll
                for (int nt = 0; nt < NT; ++nt)
                    mma_f16(acc[mt][nt], ah[mt], bh[nt]);
#pragma unroll
            for (int mt = 0; mt < MT; ++mt)
#pragma unroll
                for (int nt = 0; nt < NT; ++nt)
                    mma_f16(acc[mt][nt], al[mt], bh[nt]);
        }
        __syncthreads();
        if (tid == 0 && c + 2 < NCHUNK) issue(c + 2);
    }

    // epilogue
    const int r0 = bm + wm * WR + (lane >> 2);
#pragma unroll
    for (int mt = 0; mt < MT; ++mt) {
#pragma unroll
        for (int nt = 0; nt < NT; ++nt) {
            int row = r0 + mt * 16;
            int col = n0 + wn * WC + nt * 8 + (lane & 3) * 2;
            float bv0 = __ldg(bias + col), bv1 = __ldg(bias + col + 1);
            if (SPLIT_OUT) {
                int pl = col >> 6, kk = col & 63;
                size_t pbase = (size_t)pl * ROWSP * 128;
                uint32_t xoff = ((uint32_t)kk * 2);
#pragma unroll
                for (int half = 0; half < 2; ++half) {
                    int r = row + half * 8;
                    if (r >= NN) continue;
                    float v0 = fmaxf(acc[mt][nt][2 * half + 0] + bv0, 0.f);
                    float v1 = fmaxf(acc[mt][nt][2 * half + 1] + bv1, 0.f);
                    __half h0 = __float2half_rn(v0);
                    __half h1 = __float2half_rn(v1);
                    __half2 hv(h0, h1);
                    __half2 lv(__float2half_rn(v0 - __half2float(h0)),
                               __float2half_rn(v1 - __half2float(h1)));
                    uint32_t off = (uint32_t)r * 128 + (xoff ^ (((uint32_t)r & 7) << 4));
                    *(__half2*)((char*)Ohi + pbase + off) = hv;
                    *(__half2*)((char*)Olo + pbase + off) = lv;
                }
            } else {
#pragma unroll
                for (int half = 0; half < 2; ++half) {
                    int r = row + half * 8;
                    if (r >= NN) continue;
                    float2 v;
                    v.x = acc[mt][nt][2 * half + 0] + bv0;
                    v.y = acc[mt][nt][2 * half + 1] + bv1;
                    *(float2*)&C[(size_t)r * NB + col] = v;
                }
            }
        }
    }
    __syncthreads();
    if (tid == 0) { MBARRIER_INVAL(mb0); MBARRIER_INVAL(mb1); }
}

// ---------------- row_ptr build ---------------------------------------------
__global__ void build_row_ptr(const int* __restrict__ erow) {
    int r = blockIdx.x * blockDim.x + threadIdx.x;
    if (r > NN) return;
    int lo = 0, hi = NE;
    while (lo < hi) {
        int mid = (lo + hi) >> 1;
        if (erow[mid] < r) lo = mid + 1; else hi = mid;
    }
    g_rp[r] = lo;
}

// ---------------- fused CSR SpMM + Chebyshev recurrence ---------------------
// R13-measured best: 16 thr/row, vectorized edge loads, unroll-4.
__global__ void spmm_cheb(const int* __restrict__ ecol, const float* __restrict__ evals,
                          const float* __restrict__ gamma, float* __restrict__ z,
                          int cur, int prev, int nxt, int k, int first, int last) {
    int t = blockIdx.x * blockDim.x + threadIdx.x;
    int row = t >> 4;
    int ch = t & 15;
    if (row >= NN) return;

    const float4* vcur = (const float4*)g_tb[cur];
    int s = g_rp[row];
    int e = g_rp[row + 1];

    float4 acc = make_float4(0.f, 0.f, 0.f, 0.f);
    int i = s;
    int head = (s + 3) & ~3;
    if (head > e) head = e;
    for (; i < head; ++i) {
        int col = __ldg(ecol + i);
        float w = __ldg(evals + i);
        float4 v = __ldg(vcur + (size_t)col * 16 + ch);
        acc.x = fmaf(w, v.x, acc.x);
        acc.y = fmaf(w, v.y, acc.y);
        acc.z = fmaf(w, v.z, acc.z);
        acc.w = fmaf(w, v.w, acc.w);
    }
    for (; i + 4 <= e; i += 4) {
        int4 cc = __ldg((const int4*)(ecol + i));
        float4 ww = __ldg((const float4*)(evals + i));
        float4 v0 = __ldg(vcur + (size_t)cc.x * 16 + ch);
        float4 v1 = __ldg(vcur + (size_t)cc.y * 16 + ch);
        float4 v2 = __ldg(vcur + (size_t)cc.z * 16 + ch);
        float4 v3 = __ldg(vcur + (size_t)cc.w * 16 + ch);
        acc.x = fmaf(ww.x, v0.x, acc.x); acc.y = fmaf(ww.x, v0.y, acc.y);
        acc.z = fmaf(ww.x, v0.z, acc.z); acc.w = fmaf(ww.x, v0.w, acc.w);
        acc.x = fmaf(ww.y, v1.x, acc.x); acc.y = fmaf(ww.y, v1.y, acc.y);
        acc.z = fmaf(ww.y, v1.z, acc.z); acc.w = fmaf(ww.y, v1.w, acc.w);
        acc.x = fmaf(ww.z, v2.x, acc.x); acc.y = fmaf(ww.z, v2.y, acc.y);
        acc.z = fmaf(ww.z, v2.z, acc.z); acc.w = fmaf(ww.z, v2.w, acc.w);
        acc.x = fmaf(ww.w, v3.x, acc.x); acc.y = fmaf(ww.w, v3.y, acc.y);
        acc.z = fmaf(ww.w, v3.z, acc.z); acc.w = fmaf(ww.w, v3.w, acc.w);
    }
    for (; i < e; ++i) {
        int col = __ldg(ecol + i);
        float w = __ldg(evals + i);
        float4 v = __ldg(vcur + (size_t)col * 16 + ch);
        acc.x = fmaf(w, v.x, acc.x);
        acc.y = fmaf(w, v.y, acc.y);
        acc.z = fmaf(w, v.z, acc.z);
        acc.w = fmaf(w, v.w, acc.w);
    }

    size_t o = (size_t)row * 16 + ch;
    float4* vnext = (float4*)g_tb[nxt];
    float4* z4 = (float4*)z;

    if (first) {
        float g0 = gamma[0], g1 = gamma[1];
        float4 h = vcur[o];
        vnext[o] = acc;
        float4 zz;
        zz.x = g0 * h.x + g1 * acc.x;
        zz.y = g0 * h.y + g1 * acc.y;
        zz.z = g0 * h.z + g1 * acc.z;
        zz.w = g0 * h.w + g1 * acc.w;
        z4[o] = zz;
    } else {
        const float4* vprev = (const float4*)g_tb[prev];
        float4 p = vprev[o];
        float4 tn;
        tn.x = 2.f * acc.x - p.x;
        tn.y = 2.f * acc.y - p.y;
        tn.z = 2.f * acc.z - p.z;
        tn.w = 2.f * acc.w - p.w;
        if (!last) vnext[o] = tn;
        float g = gamma[k];
        float4 zz = z4[o];
        zz.x = fmaf(g, tn.x, zz.x);
        zz.y = fmaf(g, tn.y, zz.y);
        zz.z = fmaf(g, tn.z, zz.z);
        zz.w = fmaf(g, tn.w, zz.w);
        z4[o] = zz;
    }
}

// ---------------- launch ----------------------------------------------------
extern "C" void kernel_launch(void* const* d_in, const int* in_sizes, int n_in,
                              void* d_out, int out_size) {
    const float* x     = (const float*)d_in[0];
    const int*   erow  = (const int*)d_in[1];
    const int*   ecol  = (const int*)d_in[2];
    const float* evals = (const float*)d_in[3];
    const float* W1    = (const float*)d_in[4];
    const float* b1    = (const float*)d_in[5];
    const float* W2    = (const float*)d_in[6];
    const float* b2    = (const float*)d_in[7];
    const float* gamma = (const float*)d_in[8];
    float* z = (float*)d_out;

    float *tb0;
    __half *ahi, *alo, *hhi, *hlo, *w1, *w2;
    cudaGetSymbolAddress((void**)&tb0, g_tb);
    cudaGetSymbolAddress((void**)&ahi, g_ahi);
    cudaGetSymbolAddress((void**)&alo, g_alo);
    cudaGetSymbolAddress((void**)&hhi, g_hhi);
    cudaGetSymbolAddress((void**)&hlo, g_hlo);
    cudaGetSymbolAddress((void**)&w1, g_w1);
    cudaGetSymbolAddress((void**)&w2, g_w2);

    // dynamic smem: 1024 + 2 * (32768 + 64*128) = 82944 -> 2 CTAs/SM
    constexpr int SMEMG = 1024 + 2 * (32768 + 64 * 128);
    cudaFuncSetAttribute(tc_gemm<64, 8, 4, 2, true>,
                         cudaFuncAttributeMaxDynamicSharedMemorySize, SMEMG);
    cudaFuncSetAttribute(tc_gemm<64, 4, 4, 2, false>,
                         cudaFuncAttributeMaxDynamicSharedMemorySize, SMEMG);

    const int MTILES = (NN + 127) / 128;  // 782

    prep_w<8><<<(IND * HID + 255) / 256, 256>>>(W1, IND, w1);
    prep_w<6><<<(HID * NC + 255) / 256, 256>>>(W2, HID, w2);

    {
        long long tot = (long long)NN * (IND / 8);
        prep_a<9><<<(unsigned)((tot + 255) / 256), 256>>>(x, ahi, alo);
    }
    // GEMM1: relu(x@W1 + b1) -> split fp16 planes (g_hhi/g_hlo)
    {
        dim3 grid(4, MTILES);
        tc_gemm<64, 8, 4, 2, true><<<grid, 256, SMEMG>>>(
            ahi, alo, w1, b1, nullptr, hhi, hlo, HID);
    }
    // GEMM2: h@W2 + b2 -> g_tb[0] fp32
    {
        dim3 grid(1, MTILES);
        tc_gemm<64, 4, 4, 2, false><<<grid, 256, SMEMG>>>(
            hhi, hlo, w2, b2, tb0, nullptr, nullptr, NC);
    }

    build_row_ptr<<<(NN + 256) / 256, 256>>>(erow);

    const int SPMM_BLOCKS = (NN * 16 + 255) / 256;
    spmm_cheb<<<SPMM_BLOCKS, 256>>>(ecol, evals, gamma, z, 0, 0, 1, 1, 1, 0);
    int p = 0, c = 1;
    for (int k = 2; k <= 8; ++k) {
        int n = 3 - p - c;
        spmm_cheb<<<SPMM_BLOCKS, 256>>>(ecol, evals, gamma, z, c, p, n, k, 0, k == 8);
        p = c; c = n;
    }
}

// round 16
// speedup vs baseline: 1.9467x; 1.2863x over previous
#include <cuda_runtime.h>
#include <cuda_fp16.h>
#include <cstdint>

#define NN 100000
#define ROWSP 100096           // NN padded to multiple of 128
#define NE 3200000
#define IND 512
#define HID 256
#define NC  64

// ---------------- scratch (static device globals; no runtime allocation) ----
__device__ __align__(16) __half g_tbh[3][(size_t)NN * NC];     // rotating T_k (fp16)
__device__ int   g_rp[NN + 1];                                 // CSR row_ptr
// A operand planes: [K/64][ROWSP][64] fp16, SW128-swizzled per 128B row
__device__ __align__(128) __half g_ahi[(size_t)8 * ROWSP * 64];
__device__ __align__(128) __half g_alo[(size_t)8 * ROWSP * 64];
__device__ __align__(128) __half g_hhi[(size_t)4 * ROWSP * 64];
__device__ __align__(128) __half g_hlo[(size_t)4 * ROWSP * 64];
// W operands single fp16 plane
__device__ __align__(128) __half g_w1[8 * 256 * 64];
__device__ __align__(128) __half g_w2[4 * 64 * 64];

// ---------------- inline PTX helpers (base ISA only) ------------------------
__device__ __forceinline__ uint32_t smem_u32(const void* p) {
    uint32_t a;
    asm("{ .reg .u64 t; cvta.to.shared.u64 t, %1; cvt.u32.u64 %0, t; }" : "=r"(a) : "l"(p));
    return a;
}
#define MBARRIER_INIT(addr, cnt) \
    asm volatile("mbarrier.init.shared.b64 [%0], %1;" :: "r"(addr), "r"((uint32_t)(cnt)) : "memory")
#define MBARRIER_INVAL(addr) \
    asm volatile("mbarrier.inval.shared.b64 [%0];" :: "r"(addr) : "memory")
#define MBARRIER_EXPECT_TX(addr, bytes) \
    asm volatile("mbarrier.arrive.expect_tx.shared.b64 _, [%0], %1;" :: "r"(addr), "r"((uint32_t)(bytes)) : "memory")
__device__ __forceinline__ void mbar_wait(uint32_t mbar, uint32_t parity) {
    asm volatile(
        "{\n\t.reg .pred P1;\n\t"
        "WAIT_LOOP_%=:\n\t"
        "mbarrier.try_wait.parity.acquire.cta.shared::cta.b64 P1, [%0], %1, 0x989680;\n\t"
        "@P1 bra.uni WAIT_DONE_%=;\n\t"
        "bra.uni WAIT_LOOP_%=;\n\t"
        "WAIT_DONE_%=:\n\t}"
        :: "r"(mbar), "r"(parity) : "memory");
}
#define BULK_G2S(dst, src, bytes, mbar) \
    asm volatile("cp.async.bulk.shared::cta.global.mbarrier::complete_tx::bytes [%0], [%1], %2, [%3];" \
        :: "r"((uint32_t)(dst)), "l"(src), "r"((uint32_t)(bytes)), "r"((uint32_t)(mbar)) : "memory")

__device__ __forceinline__ void ldsm4(uint32_t* r, uint32_t addr) {
    asm volatile("ldmatrix.sync.aligned.m8n8.x4.shared.b16 {%0,%1,%2,%3}, [%4];"
        : "=r"(r[0]), "=r"(r[1]), "=r"(r[2]), "=r"(r[3]) : "r"(addr));
}
__device__ __forceinline__ void mma_f16(float* d, const uint32_t* a, const uint32_t* b) {
    asm volatile("mma.sync.aligned.m16n8k16.row.col.f32.f16.f16.f32 "
        "{%0,%1,%2,%3}, {%4,%5,%6,%7}, {%8,%9}, {%0,%1,%2,%3};"
        : "+f"(d[0]), "+f"(d[1]), "+f"(d[2]), "+f"(d[3])
        : "r"(a[0]), "r"(a[1]), "r"(a[2]), "r"(a[3]), "r"(b[0]), "r"(b[1]));
}

// ---------------- prep kernels ----------------------------------------------
template <int KSHIFT>
__global__ void prep_a(const float* __restrict__ src,
                       __half* __restrict__ dhi, __half* __restrict__ dlo) {
    constexpr int K = 1 << KSHIFT;
    constexpr int G = K / 8;
    long long idx = (long long)blockIdx.x * blockDim.x + threadIdx.x;
    if (idx >= (long long)NN * G) return;
    int r = (int)(idx / G);
    int g = (int)(idx % G);
    int k = g * 8;
    int c = k >> 6, kk = k & 63;

    const float4* s4 = (const float4*)(src + (size_t)r * K + k);
    float4 v0 = s4[0], v1 = s4[1];
    float f[8] = {v0.x, v0.y, v0.z, v0.w, v1.x, v1.y, v1.z, v1.w};
    __half2 hi[4], lo[4];
#pragma unroll
    for (int i = 0; i < 4; ++i) {
        __half h0 = __float2half_rn(f[2 * i]);
        __half h1 = __float2half_rn(f[2 * i + 1]);
        hi[i] = __half2(h0, h1);
        lo[i] = __half2(__float2half_rn(f[2 * i] - __half2float(h0)),
                        __float2half_rn(f[2 * i + 1] - __half2float(h1)));
    }
    uint32_t off = (uint32_t)r * 128 + (((uint32_t)kk * 2) ^ (((uint32_t)r & 7) << 4));
    size_t pbase = (size_t)c * ROWSP * 128;
    *(uint4*)((char*)dhi + pbase + off) = *(uint4*)hi;
    *(uint4*)((char*)dlo + pbase + off) = *(uint4*)lo;
}

template <int NSHIFT>
__global__ void prep_w(const float* __restrict__ src, int K, __half* __restrict__ dst) {
    constexpr int N = 1 << NSHIFT;
    int idx = blockIdx.x * blockDim.x + threadIdx.x;
    if (idx >= K * N) return;
    int k = idx >> NSHIFT;
    int n = idx & (N - 1);
    int c = k >> 6, kk = k & 63;
    int poff = (kk << 1) ^ ((n & 7) << 4);
    size_t d = ((size_t)c * N + n) * 64 + (poff >> 1);
    dst[d] = __float2half_rn(src[idx]);
}

// ---------------- fp16 A-split mma.sync GEMM --------------------------------
// D[128, BN] = A[128, K] @ B[BN, K]^T; A = Ahi + Alo (fp16), B single fp16.
// SPLIT_OUT: relu(acc+bias) -> swizzled fp16 hi/lo planes (feeds GEMM2).
// else:      acc+bias -> row-major fp16 (feeds spmm chain, T0).
template <int BN, int NCHUNK, int WM, int WN, bool SPLIT_OUT>
__global__ void __launch_bounds__(256, 2)
tc_gemm(const __half* __restrict__ Ahi, const __half* __restrict__ Alo,
        const __half* __restrict__ B,
        const float* __restrict__ bias, __half* __restrict__ Ch,
        __half* __restrict__ Ohi, __half* __restrict__ Olo, int NB) {
    constexpr int WR = 128 / WM;
    constexpr int WC = BN / WN;
    constexpr int MT = WR / 16;
    constexpr int NT = WC / 8;
    constexpr uint32_t BNB = BN * 128;
    constexpr uint32_t BUFB = 32768 + BNB;

    extern __shared__ char smem[];
    const uint32_t sb = smem_u32(smem);
    const int tid = threadIdx.x;
    const int lane = tid & 31;
    const int wid = tid >> 5;
    const int wm = wid / WN, wn = wid % WN;
    const int bm = blockIdx.y * 128;
    const int n0 = blockIdx.x * BN;            // n fast: CTAs share A tile in L2

    const uint32_t mb0 = sb + 8, mb1 = sb + 24;
    if (tid == 0) { MBARRIER_INIT(mb0, 1); MBARRIER_INIT(mb1, 1); }
    __syncthreads();

    auto issue = [&](int c) {
        int buf = c & 1;
        uint32_t mb = buf ? mb1 : mb0;
        uint32_t base = sb + 1024 + (uint32_t)buf * BUFB;
        MBARRIER_EXPECT_TX(mb, BUFB);
        const char* ah = (const char*)Ahi + ((size_t)c * ROWSP + bm) * 128;
        const char* al = (const char*)Alo + ((size_t)c * ROWSP + bm) * 128;
        const char* bp = (const char*)B + ((size_t)c * NB + n0) * 128;
        BULK_G2S(base,         ah, 16384, mb);
        BULK_G2S(base + 16384, al, 16384, mb);
        BULK_G2S(base + 32768, bp, BNB,   mb);
    };
    if (tid == 0) {
#pragma unroll
        for (int c = 0; c < 2 && c < NCHUNK; ++c) issue(c);
    }

    const int arow = lane & 15;
    const int akb = (lane >> 4) << 3;
    const uint32_t aRowOff = (uint32_t)(wm * WR + arow) * 128;
    const uint32_t aSw = (uint32_t)(arow & 7) << 4;
    const int brow = (lane & 7) + ((lane >> 4) << 3);
    const int bkb = ((lane >> 3) & 1) << 3;
    const uint32_t bRowOff = (uint32_t)(wn * WC + brow) * 128;
    const uint32_t bSw = (uint32_t)(brow & 7) << 4;

    float acc[MT][NT][4];
#pragma unroll
    for (int i = 0; i < MT; ++i)
#pragma unroll
        for (int j = 0; j < NT; ++j)
#pragma unroll
            for (int q = 0; q < 4; ++q) acc[i][j][q] = 0.f;

    for (int c = 0; c < NCHUNK; ++c) {
        const int buf = c & 1;
        mbar_wait(buf ? mb1 : mb0, (uint32_t)(c >> 1) & 1);

        const uint32_t base = sb + 1024 + (uint32_t)buf * BUFB;
        const uint32_t aHiS = base, aLoS = base + 16384;
        const uint32_t bS = base + 32768;

#pragma unroll
        for (int ks = 0; ks < 4; ++ks) {
            uint32_t ah[MT][4], al[MT][4], bh[NT][2];
            const uint32_t akByte = ((uint32_t)((ks * 16 + akb) * 2)) ^ aSw;
#pragma unroll
            for (int mt = 0; mt < MT; ++mt) {
                uint32_t o = aRowOff + (uint32_t)mt * 2048 + akByte;
                ldsm4(ah[mt], aHiS + o);
                ldsm4(al[mt], aLoS + o);
            }
            const uint32_t bkByte = ((uint32_t)((ks * 16 + bkb) * 2)) ^ bSw;
#pragma unroll
            for (int p = 0; p < NT / 2; ++p) {
                uint32_t o = bRowOff + (uint32_t)p * 2048 + bkByte;
                uint32_t t[4];
                ldsm4(t, bS + o);
                bh[2 * p][0] = t[0]; bh[2 * p][1] = t[1];
                bh[2 * p + 1][0] = t[2]; bh[2 * p + 1][1] = t[3];
            }
#pragma unroll
            for (int mt = 0; mt < MT; ++mt)
#pragma unroll
                for (int nt = 0; nt < NT; ++nt)
                    mma_f16(acc[mt][nt], ah[mt], bh[nt]);
#pragma unroll
            for (int mt = 0; mt < MT; ++mt)
#pragma unroll
                for (int nt = 0; nt < NT; ++nt)
                    mma_f16(acc[mt][nt], al[mt], bh[nt]);
        }
        __syncthreads();
        if (tid == 0 && c + 2 < NCHUNK) issue(c + 2);
    }

    // epilogue
    const int r0 = bm + wm * WR + (lane >> 2);
#pragma unroll
    for (int mt = 0; mt < MT; ++mt) {
#pragma unroll
        for (int nt = 0; nt < NT; ++nt) {
            int row = r0 + mt * 16;
            int col = n0 + wn * WC + nt * 8 + (lane & 3) * 2;
            float bv0 = __ldg(bias + col), bv1 = __ldg(bias + col + 1);
            if (SPLIT_OUT) {
                int pl = col >> 6, kk = col & 63;
                size_t pbase = (size_t)pl * ROWSP * 128;
                uint32_t xoff = ((uint32_t)kk * 2);
#pragma unroll
                for (int half = 0; half < 2; ++half) {
                    int r = row + half * 8;
                    if (r >= NN) continue;
                    float v0 = fmaxf(acc[mt][nt][2 * half + 0] + bv0, 0.f);
                    float v1 = fmaxf(acc[mt][nt][2 * half + 1] + bv1, 0.f);
                    __half h0 = __float2half_rn(v0);
                    __half h1 = __float2half_rn(v1);
                    __half2 hv(h0, h1);
                    __half2 lv(__float2half_rn(v0 - __half2float(h0)),
                               __float2half_rn(v1 - __half2float(h1)));
                    uint32_t off = (uint32_t)r * 128 + (xoff ^ (((uint32_t)r & 7) << 4));
                    *(__half2*)((char*)Ohi + pbase + off) = hv;
                    *(__half2*)((char*)Olo + pbase + off) = lv;
                }
            } else {
#pragma unroll
                for (int half = 0; half < 2; ++half) {
                    int r = row + half * 8;
                    if (r >= NN) continue;
                    __half2 hv = __floats2half2_rn(acc[mt][nt][2 * half + 0] + bv0,
                                                   acc[mt][nt][2 * half + 1] + bv1);
                    *(__half2*)&Ch[(size_t)r * NB + col] = hv;
                }
            }
        }
    }
    __syncthreads();
    if (tid == 0) { MBARRIER_INVAL(mb0); MBARRIER_INVAL(mb1); }
}

// ---------------- row_ptr build ---------------------------------------------
__global__ void build_row_ptr(const int* __restrict__ erow) {
    int r = blockIdx.x * blockDim.x + threadIdx.x;
    if (r > NN) return;
    int lo = 0, hi = NE;
    while (lo < hi) {
        int mid = (lo + hi) >> 1;
        if (erow[mid] < r) lo = mid + 1; else hi = mid;
    }
    g_rp[r] = lo;
}

// ---------------- fused CSR SpMM + Chebyshev recurrence (fp16 T_k) ----------
// 16 thr/row; each thread gathers uint2 (4 halves) per edge -> 128B coalesced
// per group. All math fp32; T_k stored fp16; z fp32.
__global__ void spmm_cheb(const int* __restrict__ ecol, const float* __restrict__ evals,
                          const float* __restrict__ gamma, float* __restrict__ z,
                          int cur, int prev, int nxt, int k, int first, int last) {
    int t = blockIdx.x * blockDim.x + threadIdx.x;
    int row = t >> 4;
    int ch = t & 15;
    if (row >= NN) return;

    const uint2* vcur = (const uint2*)g_tbh[cur];   // 16 uint2 per 64-half row
    int s = g_rp[row];
    int e = g_rp[row + 1];

    float4 acc = make_float4(0.f, 0.f, 0.f, 0.f);

    auto gather = [&](int col, float w) {
        uint2 u = __ldg(vcur + (size_t)col * 16 + ch);
        float2 f0 = __half22float2(*(__half2*)&u.x);
        float2 f1 = __half22float2(*(__half2*)&u.y);
        acc.x = fmaf(w, f0.x, acc.x);
        acc.y = fmaf(w, f0.y, acc.y);
        acc.z = fmaf(w, f1.x, acc.z);
        acc.w = fmaf(w, f1.y, acc.w);
    };

    int i = s;
    int head = (s + 3) & ~3;
    if (head > e) head = e;
    for (; i < head; ++i)
        gather(__ldg(ecol + i), __ldg(evals + i));
    for (; i + 4 <= e; i += 4) {
        int4 cc = __ldg((const int4*)(ecol + i));
        float4 ww = __ldg((const float4*)(evals + i));
        uint2 u0 = __ldg(vcur + (size_t)cc.x * 16 + ch);
        uint2 u1 = __ldg(vcur + (size_t)cc.y * 16 + ch);
        uint2 u2 = __ldg(vcur + (size_t)cc.z * 16 + ch);
        uint2 u3 = __ldg(vcur + (size_t)cc.w * 16 + ch);
        float2 a0 = __half22float2(*(__half2*)&u0.x), b0 = __half22float2(*(__half2*)&u0.y);
        float2 a1 = __half22float2(*(__half2*)&u1.x), b1 = __half22float2(*(__half2*)&u1.y);
        float2 a2 = __half22float2(*(__half2*)&u2.x), b2 = __half22float2(*(__half2*)&u2.y);
        float2 a3 = __half22float2(*(__half2*)&u3.x), b3 = __half22float2(*(__half2*)&u3.y);
        acc.x = fmaf(ww.x, a0.x, acc.x); acc.y = fmaf(ww.x, a0.y, acc.y);
        acc.z = fmaf(ww.x, b0.x, acc.z); acc.w = fmaf(ww.x, b0.y, acc.w);
        acc.x = fmaf(ww.y, a1.x, acc.x); acc.y = fmaf(ww.y, a1.y, acc.y);
        acc.z = fmaf(ww.y, b1.x, acc.z); acc.w = fmaf(ww.y, b1.y, acc.w);
        acc.x = fmaf(ww.z, a2.x, acc.x); acc.y = fmaf(ww.z, a2.y, acc.y);
        acc.z = fmaf(ww.z, b2.x, acc.z); acc.w = fmaf(ww.z, b2.y, acc.w);
        acc.x = fmaf(ww.w, a3.x, acc.x); acc.y = fmaf(ww.w, a3.y, acc.y);
        acc.z = fmaf(ww.w, b3.x, acc.z); acc.w = fmaf(ww.w, b3.y, acc.w);
    }
    for (; i < e; ++i)
        gather(__ldg(ecol + i), __ldg(evals + i));

    size_t o = (size_t)row * 16 + ch;
    uint2* vnext = (uint2*)g_tbh[nxt];
    float4* z4 = (float4*)z;

    auto pack = [](float a, float b, float c, float d) {
        __half2 h0 = __floats2half2_rn(a, b);
        __half2 h1 = __floats2half2_rn(c, d);
        uint2 u;
        u.x = *(uint32_t*)&h0;
        u.y = *(uint32_t*)&h1;
        return u;
    };

    if (first) {
        float g0 = gamma[0], g1 = gamma[1];
        uint2 uh = vcur[o];
        float2 h0 = __half22float2(*(__half2*)&uh.x);
        float2 h1 = __half22float2(*(__half2*)&uh.y);
        vnext[o] = pack(acc.x, acc.y, acc.z, acc.w);
        float4 zz;
        zz.x = g0 * h0.x + g1 * acc.x;
        zz.y = g0 * h0.y + g1 * acc.y;
        zz.z = g0 * h1.x + g1 * acc.z;
        zz.w = g0 * h1.y + g1 * acc.w;
        z4[o] = zz;
    } else {
        const uint2* vprev = (const uint2*)g_tbh[prev];
        uint2 up = vprev[o];
        float2 p0 = __half22float2(*(__half2*)&up.x);
        float2 p1 = __half22float2(*(__half2*)&up.y);
        float4 tn;
        tn.x = 2.f * acc.x - p0.x;
        tn.y = 2.f * acc.y - p0.y;
        tn.z = 2.f * acc.z - p1.x;
        tn.w = 2.f * acc.w - p1.y;
        if (!last) vnext[o] = pack(tn.x, tn.y, tn.z, tn.w);
        float g = gamma[k];
        float4 zz = z4[o];
        zz.x = fmaf(g, tn.x, zz.x);
        zz.y = fmaf(g, tn.y, zz.y);
        zz.z = fmaf(g, tn.z, zz.z);
        zz.w = fmaf(g, tn.w, zz.w);
        z4[o] = zz;
    }
}

// ---------------- launch ----------------------------------------------------
extern "C" void kernel_launch(void* const* d_in, const int* in_sizes, int n_in,
                              void* d_out, int out_size) {
    const float* x     = (const float*)d_in[0];
    const int*   erow  = (const int*)d_in[1];
    const int*   ecol  = (const int*)d_in[2];
    const float* evals = (const float*)d_in[3];
    const float* W1    = (const float*)d_in[4];
    const float* b1    = (const float*)d_in[5];
    const float* W2    = (const float*)d_in[6];
    const float* b2    = (const float*)d_in[7];
    const float* gamma = (const float*)d_in[8];
    float* z = (float*)d_out;

    __half *tbh0, *ahi, *alo, *hhi, *hlo, *w1, *w2;
    cudaGetSymbolAddress((void**)&tbh0, g_tbh);
    cudaGetSymbolAddress((void**)&ahi, g_ahi);
    cudaGetSymbolAddress((void**)&alo, g_alo);
    cudaGetSymbolAddress((void**)&hhi, g_hhi);
    cudaGetSymbolAddress((void**)&hlo, g_hlo);
    cudaGetSymbolAddress((void**)&w1, g_w1);
    cudaGetSymbolAddress((void**)&w2, g_w2);

    // dynamic smem: 1024 + 2 * (32768 + 64*128) = 82944 -> 2 CTAs/SM
    constexpr int SMEMG = 1024 + 2 * (32768 + 64 * 128);
    cudaFuncSetAttribute(tc_gemm<64, 8, 4, 2, true>,
                         cudaFuncAttributeMaxDynamicSharedMemorySize, SMEMG);
    cudaFuncSetAttribute(tc_gemm<64, 4, 4, 2, false>,
                         cudaFuncAttributeMaxDynamicSharedMemorySize, SMEMG);

    const int MTILES = (NN + 127) / 128;  // 782

    prep_w<8><<<(IND * HID + 255) / 256, 256>>>(W1, IND, w1);
    prep_w<6><<<(HID * NC + 255) / 256, 256>>>(W2, HID, w2);

    {
        long long tot = (long long)NN * (IND / 8);
        prep_a<9><<<(unsigned)((tot + 255) / 256), 256>>>(x, ahi, alo);
    }
    // GEMM1: relu(x@W1 + b1) -> split fp16 planes (g_hhi/g_hlo)
    {
        dim3 grid(4, MTILES);
        tc_gemm<64, 8, 4, 2, true><<<grid, 256, SMEMG>>>(
            ahi, alo, w1, b1, nullptr, hhi, hlo, HID);
    }
    // GEMM2: h@W2 + b2 -> g_tbh[0] fp16 (T0 for spmm chain)
    {
        dim3 grid(1, MTILES);
        tc_gemm<64, 4, 4, 2, false><<<grid, 256, SMEMG>>>(
            hhi, hlo, w2, b2, tbh0, nullptr, nullptr, NC);
    }

    build_row_ptr<<<(NN + 256) / 256, 256>>>(erow);

    const int SPMM_BLOCKS = (NN * 16 + 255) / 256;
    spmm_cheb<<<SPMM_BLOCKS, 256>>>(ecol, evals, gamma, z, 0, 0, 1, 1, 1, 0);
    int p = 0, c = 1;
    for (int k = 2; k <= 8; ++k) {
        int n = 3 - p - c;
        spmm_cheb<<<SPMM_BLOCKS, 256>>>(ecol, evals, gamma, z, c, p, n, k, 0, k == 8);
        p = c; c = n;
    }
}